// round 1
// baseline (speedup 1.0000x reference)
#include <cuda_runtime.h>
#include <cuda_bf16.h>

// Problem constants
#define KX 8
#define BX 8192
#define DX 1024
#define HX 256

// Scratch (device globals -- allocation-free per harness rules)
__device__ float g_recon[(size_t)KX * BX * DX];  // 256 MB
__device__ float g_err[KX * BX];

// Tile config for the fused expert kernel
// Block: 256 threads (8 warps). Each block handles one expert k and 64 batch rows.
// Stage 1: h[64,256] = relu(x[64,1024] @ W1k[1024,256] + b1)   (h kept in smem)
// Stage 2: recon[64,1024] = h @ W2k[256,1024] + b2, streamed in 128-col chunks,
//          written to g_recon, per-row sum((recon-x)^2) accumulated in regs.
#define BM 64
#define SM_H   (BM * HX)      // 16384 floats, 64 KB
#define SM_W   (16 * HX)      // 4096 floats, 16 KB (reused for W1 16x256 and W2 16x128 tiles)
#define SM_X   (BM * 16)      // 1024 floats, 4 KB
#define SMEM_FLOATS (SM_H + SM_W + SM_X)

__global__ __launch_bounds__(256, 2)
void ae_expert_kernel(const float* __restrict__ x,
                      const float* __restrict__ W1,
                      const float* __restrict__ b1,
                      const float* __restrict__ W2,
                      const float* __restrict__ b2)
{
    extern __shared__ float smem[];
    float* h_s = smem;                 // [64][256]
    float* w_s = smem + SM_H;          // [16][256] or [16][128]
    float* x_s = w_s + SM_W;           // [64][16]

    const int k    = blockIdx.y;
    const int b0   = blockIdx.x * BM;
    const int tid  = threadIdx.x;
    const int warp = tid >> 5;
    const int lane = tid & 31;

    const float* W1k = W1 + (size_t)k * DX * HX;
    const float* W2k = W2 + (size_t)k * HX * DX;

    // ---------------- Stage 1: h = relu(x @ W1k + b1) ----------------
    // Per-thread micro-tile: 8 rows (warp*8+i) x 8 cols (lane + 32*j)
    float acc[8][8];
    #pragma unroll
    for (int i = 0; i < 8; i++)
        #pragma unroll
        for (int j = 0; j < 8; j++) acc[i][j] = 0.0f;

    for (int kk0 = 0; kk0 < DX; kk0 += 16) {
        // load x tile [64][16]
        {
            int r = tid >> 2;            // 0..63
            int c = (tid & 3) * 4;       // 0,4,8,12
            float4 v = *(const float4*)(x + (size_t)(b0 + r) * DX + kk0 + c);
            *(float4*)(x_s + r * 16 + c) = v;
        }
        // load W1 tile [16][256]
        {
            int r = tid >> 4;            // 0..15
            int c = (tid & 15) * 16;     // 0..240 step 16
            const float4* src = (const float4*)(W1k + (size_t)(kk0 + r) * HX + c);
            float4* dst = (float4*)(w_s + r * HX + c);
            dst[0] = src[0]; dst[1] = src[1]; dst[2] = src[2]; dst[3] = src[3];
        }
        __syncthreads();
        #pragma unroll
        for (int kk = 0; kk < 16; kk++) {
            float a[8], bb[8];
            #pragma unroll
            for (int i = 0; i < 8; i++) a[i] = x_s[(warp * 8 + i) * 16 + kk];
            #pragma unroll
            for (int j = 0; j < 8; j++) bb[j] = w_s[kk * HX + lane + 32 * j];
            #pragma unroll
            for (int i = 0; i < 8; i++)
                #pragma unroll
                for (int j = 0; j < 8; j++)
                    acc[i][j] = fmaf(a[i], bb[j], acc[i][j]);
        }
        __syncthreads();
    }

    // bias + relu -> h_s  (each warp writes only its own 8 rows)
    #pragma unroll
    for (int j = 0; j < 8; j++) {
        float bv = b1[k * HX + lane + 32 * j];
        #pragma unroll
        for (int i = 0; i < 8; i++) {
            float v = acc[i][j] + bv;
            h_s[(warp * 8 + i) * HX + lane + 32 * j] = v > 0.0f ? v : 0.0f;
        }
    }
    // no sync needed: stage 2 reads only this warp's own h rows; w_s reuse is
    // protected by the sync at the top of the stage-2 kk loop.

    // ---------------- Stage 2: recon = h @ W2k + b2, err accumulation ----------------
    float errsum[8];
    #pragma unroll
    for (int i = 0; i < 8; i++) errsum[i] = 0.0f;

    for (int n0 = 0; n0 < DX; n0 += 128) {
        float acc2[8][4];
        #pragma unroll
        for (int i = 0; i < 8; i++)
            #pragma unroll
            for (int j = 0; j < 4; j++) acc2[i][j] = 0.0f;

        for (int kk0 = 0; kk0 < HX; kk0 += 16) {
            __syncthreads();   // previous w_s consumers done
            {
                int r = tid >> 4;            // 0..15
                int c = (tid & 15) * 8;      // 0..120 step 8
                const float4* src = (const float4*)(W2k + (size_t)(kk0 + r) * DX + n0 + c);
                float4* dst = (float4*)(w_s + r * 128 + c);
                dst[0] = src[0]; dst[1] = src[1];
            }
            __syncthreads();
            #pragma unroll
            for (int kk = 0; kk < 16; kk++) {
                float4 bv = *(const float4*)(w_s + kk * 128 + lane * 4);
                #pragma unroll
                for (int i = 0; i < 8; i++) {
                    float a = h_s[(warp * 8 + i) * HX + kk0 + kk];
                    acc2[i][0] = fmaf(a, bv.x, acc2[i][0]);
                    acc2[i][1] = fmaf(a, bv.y, acc2[i][1]);
                    acc2[i][2] = fmaf(a, bv.z, acc2[i][2]);
                    acc2[i][3] = fmaf(a, bv.w, acc2[i][3]);
                }
            }
        }

        // epilogue for this 128-col chunk
        float4 bias = *(const float4*)(b2 + (size_t)k * DX + n0 + lane * 4);
        #pragma unroll
        for (int i = 0; i < 8; i++) {
            int row = b0 + warp * 8 + i;
            float4 xv = *(const float4*)(x + (size_t)row * DX + n0 + lane * 4);
            float4 rv;
            rv.x = acc2[i][0] + bias.x;
            rv.y = acc2[i][1] + bias.y;
            rv.z = acc2[i][2] + bias.z;
            rv.w = acc2[i][3] + bias.w;
            *(float4*)(g_recon + ((size_t)k * BX + row) * DX + n0 + lane * 4) = rv;
            float dx0 = rv.x - xv.x, dx1 = rv.y - xv.y;
            float dx2 = rv.z - xv.z, dx3 = rv.w - xv.w;
            errsum[i] = fmaf(dx0, dx0, errsum[i]);
            errsum[i] = fmaf(dx1, dx1, errsum[i]);
            errsum[i] = fmaf(dx2, dx2, errsum[i]);
            errsum[i] = fmaf(dx3, dx3, errsum[i]);
        }
    }

    // reduce err over the 32 lanes sharing each row
    #pragma unroll
    for (int i = 0; i < 8; i++) {
        float v = errsum[i];
        v += __shfl_xor_sync(0xffffffffu, v, 16);
        v += __shfl_xor_sync(0xffffffffu, v, 8);
        v += __shfl_xor_sync(0xffffffffu, v, 4);
        v += __shfl_xor_sync(0xffffffffu, v, 2);
        v += __shfl_xor_sync(0xffffffffu, v, 1);
        if (lane == 0)
            g_err[(size_t)k * BX + b0 + warp * 8 + i] = v * (1.0f / DX);
    }
}

// Per-row argmin over K experts + float4 gather of the winner's reconstruction.
// One warp per batch row; 8 rows per block.
__global__ __launch_bounds__(256)
void ae_assign_gather_kernel(float* __restrict__ out)
{
    const int warp = threadIdx.x >> 5;
    const int lane = threadIdx.x & 31;
    const int b = blockIdx.x * 8 + warp;
    if (b >= BX) return;

    // every lane redundantly computes the argmin (8 L2-cached loads)
    float best = g_err[b];
    int bi = 0;
    #pragma unroll
    for (int k = 1; k < KX; k++) {
        float e = g_err[(size_t)k * BX + b];
        if (e < best) { best = e; bi = k; }
    }

    const float4* src = (const float4*)(g_recon + ((size_t)bi * BX + b) * DX);
    float4* dst = (float4*)(out + (size_t)b * DX);
    #pragma unroll
    for (int j = 0; j < 8; j++)
        dst[lane + 32 * j] = src[lane + 32 * j];
}

extern "C" void kernel_launch(void* const* d_in, const int* in_sizes, int n_in,
                              void* d_out, int out_size)
{
    const float* x  = (const float*)d_in[0];
    const float* W1 = (const float*)d_in[1];
    const float* b1 = (const float*)d_in[2];
    const float* W2 = (const float*)d_in[3];
    const float* b2 = (const float*)d_in[4];
    float* out = (float*)d_out;

    const size_t smem_bytes = (size_t)SMEM_FLOATS * sizeof(float);  // 84 KB
    cudaFuncSetAttribute(ae_expert_kernel,
                         cudaFuncAttributeMaxDynamicSharedMemorySize,
                         (int)smem_bytes);

    dim3 grid(BX / BM, KX);   // (128, 8)
    ae_expert_kernel<<<grid, 256, smem_bytes>>>(x, W1, b1, W2, b2);
    ae_assign_gather_kernel<<<BX / 8, 256>>>(out);
}

// round 2
// speedup vs baseline: 1.1153x; 1.1153x over previous
#include <cuda_runtime.h>
#include <cuda_bf16.h>

// Problem constants
#define KX 8
#define BX 8192
#define DX 1024
#define HX 256

typedef unsigned long long u64;

// Scratch (device globals -- allocation-free per harness rules)
__device__ float g_recon[(size_t)KX * BX * DX];  // 256 MB
__device__ float g_err[KX * BX];

// ---------------------------------------------------------------------------
// Packed f32x2 helpers (sm_100+): 2 fp32 FMAs per instruction -> 128 FMA/cyc/SM
// ---------------------------------------------------------------------------
__device__ __forceinline__ u64 dup2(float v) {
    u64 r;
    asm("mov.b64 %0, {%1, %1};" : "=l"(r) : "f"(v));
    return r;
}
__device__ __forceinline__ void ffma2(u64& d, u64 a, u64 b) {
    asm("fma.rn.f32x2 %0, %1, %2, %0;" : "+l"(d) : "l"(a), "l"(b));
}
__device__ __forceinline__ float2 unpk(u64 p) {
    float2 f;
    asm("mov.b64 {%0, %1}, %2;" : "=f"(f.x), "=f"(f.y) : "l"(p));
    return f;
}

// ---------------------------------------------------------------------------
// Fused expert kernel. Block = 256 threads (8 warps), one expert k x 64 rows.
// Stage 1: h[64,256] = relu(x[64,1024] @ W1k + b1), h kept transposed in smem.
// Stage 2: recon = h @ W2k + b2 streamed in 128-col chunks -> g_recon,
//          per-row squared error accumulated in registers -> g_err.
// Accumulators are f32x2 pairs over adjacent batch ROWS; a-operands are
// contiguous row pairs in transposed smem (broadcast LDS.64), b-operands are
// lane-duplicated via mov.b64.
// ---------------------------------------------------------------------------
#define BM 64
#define HSTRIDE 66                         // padded row stride of h_sT (even!)
#define SM_H  (HX * HSTRIDE)               // 16896 floats: h_sT[col][row]
#define SM_W  (16 * HX)                    // 4096 floats (w1 16x256 / w2 16x128)
#define SM_X  (16 * BM)                    // 1024 floats: x_sT[kk][row]
#define SMEM_FLOATS (SM_H + SM_W + SM_X)   // 22016 floats = 86 KB

__global__ __launch_bounds__(256, 2)
void ae_expert_kernel(const float* __restrict__ x,
                      const float* __restrict__ W1,
                      const float* __restrict__ b1,
                      const float* __restrict__ W2,
                      const float* __restrict__ b2)
{
    extern __shared__ float smem[];
    float* h_sT = smem;                 // [256][66] : h_sT[col*66 + row]
    float* w_s  = smem + SM_H;          // [16][256] or [16][128]
    float* x_sT = w_s + SM_W;           // [16][64]  : x_sT[kk*64 + row]

    const int k    = blockIdx.y;
    const int b0   = blockIdx.x * BM;
    const int tid  = threadIdx.x;
    const int warp = tid >> 5;
    const int lane = tid & 31;

    const float* W1k = W1 + (size_t)k * DX * HX;
    const float* W2k = W2 + (size_t)k * HX * DX;

    // ---------------- Stage 1: h = relu(x @ W1k + b1) ----------------
    // acc1[ip][j]: f32x2 pair = rows (warp*8+2ip, warp*8+2ip+1), col lane+32j
    u64 acc1[4][8];
    #pragma unroll
    for (int ip = 0; ip < 4; ip++)
        #pragma unroll
        for (int j = 0; j < 8; j++) acc1[ip][j] = 0ull;

    for (int kk0 = 0; kk0 < DX; kk0 += 16) {
        // load x tile [64][16] transposed -> x_sT[kk][row]
        {
            int r = tid >> 2;            // 0..63
            int c = (tid & 3) * 4;       // 0,4,8,12
            float4 v = *(const float4*)(x + (size_t)(b0 + r) * DX + kk0 + c);
            x_sT[(c + 0) * BM + r] = v.x;
            x_sT[(c + 1) * BM + r] = v.y;
            x_sT[(c + 2) * BM + r] = v.z;
            x_sT[(c + 3) * BM + r] = v.w;
        }
        // load W1 tile [16][256]
        {
            int r = tid >> 4;            // 0..15
            int c = (tid & 15) * 16;     // 0..240 step 16
            const float4* src = (const float4*)(W1k + (size_t)(kk0 + r) * HX + c);
            float4* dst = (float4*)(w_s + r * HX + c);
            dst[0] = src[0]; dst[1] = src[1]; dst[2] = src[2]; dst[3] = src[3];
        }
        __syncthreads();
        #pragma unroll
        for (int kk = 0; kk < 16; kk++) {
            u64 a[4];
            #pragma unroll
            for (int ip = 0; ip < 4; ip++)
                a[ip] = *(const u64*)(x_sT + kk * BM + warp * 8 + 2 * ip);
            u64 bb[8];
            #pragma unroll
            for (int j = 0; j < 8; j++)
                bb[j] = dup2(w_s[kk * HX + lane + 32 * j]);
            #pragma unroll
            for (int ip = 0; ip < 4; ip++)
                #pragma unroll
                for (int j = 0; j < 8; j++)
                    ffma2(acc1[ip][j], a[ip], bb[j]);
        }
        __syncthreads();
    }

    // bias + relu -> h_sT[col][row] (transposed, 2-way-conflict padded stride)
    #pragma unroll
    for (int j = 0; j < 8; j++) {
        float bv = b1[k * HX + lane + 32 * j];
        int col = lane + 32 * j;
        #pragma unroll
        for (int ip = 0; ip < 4; ip++) {
            float2 f = unpk(acc1[ip][j]);
            float v0 = f.x + bv; v0 = v0 > 0.0f ? v0 : 0.0f;
            float v1 = f.y + bv; v1 = v1 > 0.0f ? v1 : 0.0f;
            h_sT[col * HSTRIDE + warp * 8 + 2 * ip]     = v0;
            h_sT[col * HSTRIDE + warp * 8 + 2 * ip + 1] = v1;
        }
    }
    // h rows are private per warp; block-wide visibility handled by the
    // __syncthreads() at the top of the stage-2 tile loop.

    // ---------------- Stage 2: recon = h @ W2k + b2, err accumulation --------
    float errsum[8];
    #pragma unroll
    for (int i = 0; i < 8; i++) errsum[i] = 0.0f;

    for (int n0 = 0; n0 < DX; n0 += 128) {
        // acc2[ip][q]: pair = rows (2ip,2ip+1), col = n0 + lane*4 + q
        u64 acc2[4][4];
        #pragma unroll
        for (int ip = 0; ip < 4; ip++)
            #pragma unroll
            for (int q = 0; q < 4; q++) acc2[ip][q] = 0ull;

        for (int kk0 = 0; kk0 < HX; kk0 += 16) {
            __syncthreads();   // previous w_s consumers done (also fences h_sT)
            {
                int r = tid >> 4;            // 0..15
                int c = (tid & 15) * 8;      // 0..120 step 8
                const float4* src = (const float4*)(W2k + (size_t)(kk0 + r) * DX + n0 + c);
                float4* dst = (float4*)(w_s + r * 128 + c);
                dst[0] = src[0]; dst[1] = src[1];
            }
            __syncthreads();
            #pragma unroll
            for (int kk = 0; kk < 16; kk++) {
                u64 a[4];
                #pragma unroll
                for (int ip = 0; ip < 4; ip++)
                    a[ip] = *(const u64*)(h_sT + (kk0 + kk) * HSTRIDE + warp * 8 + 2 * ip);
                float4 bv = *(const float4*)(w_s + kk * 128 + lane * 4);
                u64 bb0 = dup2(bv.x), bb1 = dup2(bv.y), bb2 = dup2(bv.z), bb3 = dup2(bv.w);
                #pragma unroll
                for (int ip = 0; ip < 4; ip++) {
                    ffma2(acc2[ip][0], a[ip], bb0);
                    ffma2(acc2[ip][1], a[ip], bb1);
                    ffma2(acc2[ip][2], a[ip], bb2);
                    ffma2(acc2[ip][3], a[ip], bb3);
                }
            }
        }

        // epilogue for this 128-col chunk
        float4 bias = *(const float4*)(b2 + (size_t)k * DX + n0 + lane * 4);
        #pragma unroll
        for (int ip = 0; ip < 4; ip++) {
            float2 f0 = unpk(acc2[ip][0]);
            float2 f1 = unpk(acc2[ip][1]);
            float2 f2 = unpk(acc2[ip][2]);
            float2 f3 = unpk(acc2[ip][3]);
            #pragma unroll
            for (int half = 0; half < 2; half++) {
                int lr  = 2 * ip + half;               // 0..7 (local row in warp)
                int row = b0 + warp * 8 + lr;
                float4 rv;
                rv.x = (half ? f0.y : f0.x) + bias.x;
                rv.y = (half ? f1.y : f1.x) + bias.y;
                rv.z = (half ? f2.y : f2.x) + bias.z;
                rv.w = (half ? f3.y : f3.x) + bias.w;
                float4 xv = *(const float4*)(x + (size_t)row * DX + n0 + lane * 4);
                *(float4*)(g_recon + ((size_t)k * BX + row) * DX + n0 + lane * 4) = rv;
                float d0 = rv.x - xv.x, d1 = rv.y - xv.y;
                float d2 = rv.z - xv.z, d3 = rv.w - xv.w;
                errsum[lr] = fmaf(d0, d0, errsum[lr]);
                errsum[lr] = fmaf(d1, d1, errsum[lr]);
                errsum[lr] = fmaf(d2, d2, errsum[lr]);
                errsum[lr] = fmaf(d3, d3, errsum[lr]);
            }
        }
    }

    // reduce err over the 32 lanes sharing each row
    #pragma unroll
    for (int lr = 0; lr < 8; lr++) {
        float v = errsum[lr];
        v += __shfl_xor_sync(0xffffffffu, v, 16);
        v += __shfl_xor_sync(0xffffffffu, v, 8);
        v += __shfl_xor_sync(0xffffffffu, v, 4);
        v += __shfl_xor_sync(0xffffffffu, v, 2);
        v += __shfl_xor_sync(0xffffffffu, v, 1);
        if (lane == 0)
            g_err[(size_t)k * BX + b0 + warp * 8 + lr] = v * (1.0f / DX);
    }
}

// Per-row argmin over K experts + float4 gather of the winner's reconstruction.
__global__ __launch_bounds__(256)
void ae_assign_gather_kernel(float* __restrict__ out)
{
    const int warp = threadIdx.x >> 5;
    const int lane = threadIdx.x & 31;
    const int b = blockIdx.x * 8 + warp;
    if (b >= BX) return;

    float best = g_err[b];
    int bi = 0;
    #pragma unroll
    for (int k = 1; k < KX; k++) {
        float e = g_err[(size_t)k * BX + b];
        if (e < best) { best = e; bi = k; }
    }

    const float4* src = (const float4*)(g_recon + ((size_t)bi * BX + b) * DX);
    float4* dst = (float4*)(out + (size_t)b * DX);
    #pragma unroll
    for (int j = 0; j < 8; j++)
        dst[lane + 32 * j] = src[lane + 32 * j];
}

extern "C" void kernel_launch(void* const* d_in, const int* in_sizes, int n_in,
                              void* d_out, int out_size)
{
    const float* x  = (const float*)d_in[0];
    const float* W1 = (const float*)d_in[1];
    const float* b1 = (const float*)d_in[2];
    const float* W2 = (const float*)d_in[3];
    const float* b2 = (const float*)d_in[4];
    float* out = (float*)d_out;

    const size_t smem_bytes = (size_t)SMEM_FLOATS * sizeof(float);  // 86 KB
    cudaFuncSetAttribute(ae_expert_kernel,
                         cudaFuncAttributeMaxDynamicSharedMemorySize,
                         (int)smem_bytes);

    dim3 grid(BX / BM, KX);   // (128, 8)
    ae_expert_kernel<<<grid, 256, smem_bytes>>>(x, W1, b1, W2, b2);
    ae_assign_gather_kernel<<<BX / 8, 256>>>(out);
}

// round 4
// speedup vs baseline: 2.6425x; 2.3693x over previous
#include <cuda_runtime.h>
#include <cuda_bf16.h>
#include <cstdint>

// ---------------------------------------------------------------------------
// Problem constants
// ---------------------------------------------------------------------------
#define KX 8
#define BX 8192
#define DX 1024
#define HX 256
#define BM 128            // batch rows per CTA

// ---------------------------------------------------------------------------
// Arch-feature gate: tcgen05 only exists in the sm_103a/sm_10xf device pass.
// The generic compute_103 PTX pass compiles a correct scalar fallback instead.
// ---------------------------------------------------------------------------
#if defined(__CUDA_ARCH__) && (__CUDA_ARCH__ >= 1000) && \
    (defined(__CUDA_ARCH_FEAT_SM103_ALL) || defined(__CUDA_ARCH_FEAT_SM100_ALL) || \
     defined(__CUDA_ARCH_SPECIFIC__) || defined(__CUDA_ARCH_FAMILY_SPECIFIC__))
#define AE_TC 1
#else
#define AE_TC 0
#endif

// ---------------------------------------------------------------------------
// Device scratch (allocation-free per harness rules)
// ---------------------------------------------------------------------------
__device__ float g_recon[(size_t)KX * BX * DX];                 // 256 MB
__device__ float g_err[KX * BX];
__device__ __nv_bfloat16 g_xs [(size_t)3 * BX * DX];            // x split (48 MB)
__device__ __nv_bfloat16 g_w1t[(size_t)3 * KX * HX * DX];       // W1^T split (12.6 MB)
__device__ __nv_bfloat16 g_w2t[(size_t)3 * KX * DX * HX];       // W2^T split (12.6 MB)

// ---------------------------------------------------------------------------
// Generic helpers
// ---------------------------------------------------------------------------
__device__ __forceinline__ uint32_t smem_u32(const void* p) {
    uint32_t a;
    asm("{ .reg .u64 t; cvta.to.shared.u64 t, %1; cvt.u32.u64 %0, t; }" : "=r"(a) : "l"(p));
    return a;
}

#define SW128(off) ((off) ^ (((off) >> 3) & 0x70))

#define CP16(dst, src) \
    asm volatile("cp.async.cg.shared.global [%0], [%1], 16;" :: "r"(dst), "l"(src))
#define CP_COMMIT() asm volatile("cp.async.commit_group;")
#define CP_WAIT0()  asm volatile("cp.async.wait_group 0;" ::: "memory")

#define MBARRIER_INIT(a, c) \
    asm volatile("mbarrier.init.shared.b64 [%0], %1;" :: "r"((uint32_t)(a)), "r"((uint32_t)(c)) : "memory")
#define MBARRIER_INVAL(a) \
    asm volatile("mbarrier.inval.shared.b64 [%0];" :: "r"((uint32_t)(a)) : "memory")

#define MBARRIER_WAIT_PARITY(mbar_smem_addr, phase_parity) do { \
    uint32_t _mbar = (uint32_t)(mbar_smem_addr); \
    uint32_t _parity = (uint32_t)(phase_parity); \
    uint32_t _done; \
    asm volatile( \
        "{\n\t.reg .pred p;\n\t" \
        "mbarrier.try_wait.parity.acquire.cta.shared::cta.b64 p, [%1], %2;\n\t" \
        "selp.b32 %0, 1, 0, p;\n\t}" \
        : "=r"(_done) : "r"(_mbar), "r"(_parity) : "memory"); \
    if (!_done) { \
        asm volatile( \
            "{\n\t.reg .pred P1;\n\t" \
            "WAIT_LOOP_%=:\n\t" \
            "mbarrier.try_wait.parity.acquire.cta.shared::cta.b64 P1, [%0], %1, 0x989680;\n\t" \
            "@P1 bra.uni WAIT_DONE_%=;\n\t" \
            "bra.uni WAIT_LOOP_%=;\n\t" \
            "WAIT_DONE_%=:\n\t}" \
            :: "r"(_mbar), "r"(_parity) : "memory"); \
    } \
} while (0)

// bf16x3 Dekker split (exact residuals in fp32)
__device__ __forceinline__ void split3(float v, __nv_bfloat16& h0, __nv_bfloat16& h1,
                                       __nv_bfloat16& h2) {
    h0 = __float2bfloat16_rn(v);
    float r1 = v - __bfloat162float(h0);
    h1 = __float2bfloat16_rn(r1);
    float r2 = r1 - __bfloat162float(h1);
    h2 = __float2bfloat16_rn(r2);
}
__device__ __forceinline__ uint32_t pack2(__nv_bfloat16 lo, __nv_bfloat16 hi) {
    return (uint32_t)__bfloat16_as_ushort(lo) | ((uint32_t)__bfloat16_as_ushort(hi) << 16);
}

// ---------------------------------------------------------------------------
// tcgen05 helpers (only emitted in the arch-specific pass)
// ---------------------------------------------------------------------------
#if AE_TC
#define TCGEN05_ALLOC(sa, n) \
    asm volatile("tcgen05.alloc.cta_group::1.sync.aligned.shared::cta.b32 [%0], %1;" \
                 :: "r"((uint32_t)(sa)), "r"((uint32_t)(n)) : "memory")
#define TCGEN05_DEALLOC(t, n) \
    asm volatile("tcgen05.dealloc.cta_group::1.sync.aligned.b32 %0, %1;" :: "r"(t), "r"((uint32_t)(n)))
#define TCGEN05_RELINQ() \
    asm volatile("tcgen05.relinquish_alloc_permit.cta_group::1.sync.aligned;")
#define TCGEN05_COMMIT(mb) \
    asm volatile("tcgen05.commit.cta_group::1.mbarrier::arrive::one.shared::cluster.b64 [%0];" \
                 :: "r"((uint32_t)(mb)) : "memory")
#define TCGEN05_WAIT_LD() asm volatile("tcgen05.wait::ld.sync.aligned;" ::: "memory")
#define TCGEN05_WAIT_ST() asm volatile("tcgen05.wait::st.sync.aligned;" ::: "memory")
#define TCGEN05_FENCE_BEFORE() asm volatile("tcgen05.fence::before_thread_sync;" ::: "memory")
#define TCGEN05_FENCE_AFTER()  asm volatile("tcgen05.fence::after_thread_sync;" ::: "memory")
#define FENCE_PROXY_ASYNC() asm volatile("fence.proxy.async.shared::cta;" ::: "memory")

#define LDTM32(r, ta) \
    asm volatile( \
        "tcgen05.ld.sync.aligned.32x32b.x32.b32 " \
        "{%0, %1, %2, %3, %4, %5, %6, %7, " \
        " %8, %9, %10, %11, %12, %13, %14, %15, " \
        " %16, %17, %18, %19, %20, %21, %22, %23, " \
        " %24, %25, %26, %27, %28, %29, %30, %31}, [%32];" \
        : "=r"((r)[0]),  "=r"((r)[1]),  "=r"((r)[2]),  "=r"((r)[3]), \
          "=r"((r)[4]),  "=r"((r)[5]),  "=r"((r)[6]),  "=r"((r)[7]), \
          "=r"((r)[8]),  "=r"((r)[9]),  "=r"((r)[10]), "=r"((r)[11]), \
          "=r"((r)[12]), "=r"((r)[13]), "=r"((r)[14]), "=r"((r)[15]), \
          "=r"((r)[16]), "=r"((r)[17]), "=r"((r)[18]), "=r"((r)[19]), \
          "=r"((r)[20]), "=r"((r)[21]), "=r"((r)[22]), "=r"((r)[23]), \
          "=r"((r)[24]), "=r"((r)[25]), "=r"((r)[26]), "=r"((r)[27]), \
          "=r"((r)[28]), "=r"((r)[29]), "=r"((r)[30]), "=r"((r)[31]) \
        : "r"(ta))

#define STTM16(ta, r) \
    asm volatile( \
        "tcgen05.st.sync.aligned.32x32b.x16.b32 [%0], " \
        "{%1, %2, %3, %4, %5, %6, %7, %8, " \
        " %9, %10, %11, %12, %13, %14, %15, %16};" \
        :: "r"(ta), \
           "r"((r)[0]),  "r"((r)[1]),  "r"((r)[2]),  "r"((r)[3]), \
           "r"((r)[4]),  "r"((r)[5]),  "r"((r)[6]),  "r"((r)[7]), \
           "r"((r)[8]),  "r"((r)[9]),  "r"((r)[10]), "r"((r)[11]), \
           "r"((r)[12]), "r"((r)[13]), "r"((r)[14]), "r"((r)[15]) \
        : "memory")

// SMEM descriptor, SW128, LBO=1, SBO=64 (K-major, 128B rows)
static constexpr uint64_t DESC_BASE_SW128 =
    (uint64_t(2) << 61) | (uint64_t(1) << 46) | (uint64_t(64) << 32) | (uint64_t(1) << 16);
#define MAKE_DESC(addr) (DESC_BASE_SW128 | ((uint64_t)((addr) >> 4) & 0x3FFF))

__device__ __forceinline__ void mma_f16_ss(uint32_t d, uint64_t ad, uint64_t bd,
                                           uint32_t idesc, bool en) {
    uint32_t e = en ? 1u : 0u;
    asm volatile(
        "{\n\t.reg .pred p;\n\tsetp.ne.u32 p, %4, 0;\n\t"
        "tcgen05.mma.cta_group::1.kind::f16 [%0], %1, %2, %3, {%5, %5, %5, %5}, p;\n\t}"
        :: "r"(d), "l"(ad), "l"(bd), "r"(idesc), "r"(e), "r"(0u) : "memory");
}
__device__ __forceinline__ void mma_f16_ts(uint32_t d, uint32_t at, uint64_t bd,
                                           uint32_t idesc, bool en) {
    uint32_t e = en ? 1u : 0u;
    asm volatile(
        "{\n\t.reg .pred p;\n\tsetp.ne.u32 p, %4, 0;\n\t"
        "tcgen05.mma.cta_group::1.kind::f16 [%0], [%1], %2, %3, {%5, %5, %5, %5}, p;\n\t}"
        :: "r"(d), "r"(at), "l"(bd), "r"(idesc), "r"(e), "r"(0u) : "memory");
}
#endif  // AE_TC

// ---------------------------------------------------------------------------
// SMEM layout (bytes)
// ---------------------------------------------------------------------------
#define SM_A1      0           // stage1 A levels (3 x 16KB) / stage2 B levels (3 x 16KB)
#define SM_B1      49152       // stage1 B levels (3 x 32KB)
#define SM_XS      49152       // stage2 x stage [128][132] f32 (overlaps SM_B1, stage1 dead)
#define SM_RC      116736      // stage2 recon stage [128][132] f32
#define SM_BIAS1   184320      // b1 copy (1 KB)
#define SM_MBAR    185344
#define SM_TMEMPTR 185352
#define SMEM_TOTAL 185408

// TMEM column layout (512 cols)
#define TM_D1   0      // stage1 accum h [128 x 256] f32
#define TM_D2   128    // stage2 accum recon chunk [128 x 128] f32
#define TM_A2   0      // h split level2 (bf16x2, 128 cols) — overlaps dying D1, chunk-safe
#define TM_A0   256    // h split level0
#define TM_A1C  384    // h split level1

// idesc: dtype F32 | atype BF16 | btype BF16 | N/8<<17 | M/16<<24
#define IDESC1  ((8u << 24) | (32u << 17) | (1u << 10) | (1u << 7) | (1u << 4))  // M128 N256
#define IDESC2  ((8u << 24) | (16u << 17) | (1u << 10) | (1u << 7) | (1u << 4))  // M128 N128

// ---------------------------------------------------------------------------
// Prep kernels
// ---------------------------------------------------------------------------
__global__ void split_x_kernel(const float* __restrict__ x) {
    size_t i2 = (size_t)blockIdx.x * blockDim.x + threadIdx.x;   // pair index
    if (i2 >= (size_t)BX * DX / 2) return;
    float2 v = ((const float2*)x)[i2];
    __nv_bfloat16 a0, a1, a2, b0, b1, b2;
    split3(v.x, a0, a1, a2);
    split3(v.y, b0, b1, b2);
    const size_t N = (size_t)BX * DX;
    ((uint32_t*)g_xs)[i2]         = pack2(a0, b0);
    ((uint32_t*)g_xs)[N / 2 + i2] = pack2(a1, b1);
    ((uint32_t*)g_xs)[N + i2]     = pack2(a2, b2);
}

__global__ void tr_w1_kernel(const float* __restrict__ W1) {
    __shared__ float t[32][33];
    int h0 = blockIdx.x * 32, d0 = blockIdx.y * 32, k = blockIdx.z;
    int tx = threadIdx.x, ty = threadIdx.y;
    #pragma unroll
    for (int r = 0; r < 4; r++) {
        int d = d0 + ty + r * 8;
        t[ty + r * 8][tx] = W1[((size_t)k * DX + d) * HX + h0 + tx];
    }
    __syncthreads();
    const size_t LVL = (size_t)KX * HX * DX;
    #pragma unroll
    for (int r = 0; r < 4; r++) {
        int h = h0 + ty + r * 8;
        float v = t[tx][ty + r * 8];                 // (d = d0+tx, h)
        __nv_bfloat16 a0, a1, a2;
        split3(v, a0, a1, a2);
        size_t base = ((size_t)k * HX + h) * DX + d0 + tx;
        g_w1t[base] = a0; g_w1t[LVL + base] = a1; g_w1t[2 * LVL + base] = a2;
    }
}

__global__ void tr_w2_kernel(const float* __restrict__ W2) {
    __shared__ float t[32][33];
    int d0 = blockIdx.x * 32, h0 = blockIdx.y * 32, k = blockIdx.z;
    int tx = threadIdx.x, ty = threadIdx.y;
    #pragma unroll
    for (int r = 0; r < 4; r++) {
        int h = h0 + ty + r * 8;
        t[ty + r * 8][tx] = W2[((size_t)k * HX + h) * DX + d0 + tx];
    }
    __syncthreads();
    const size_t LVL = (size_t)KX * DX * HX;
    #pragma unroll
    for (int r = 0; r < 4; r++) {
        int d = d0 + ty + r * 8;
        float v = t[tx][ty + r * 8];                 // (h = h0+tx, d)
        __nv_bfloat16 a0, a1, a2;
        split3(v, a0, a1, a2);
        size_t base = ((size_t)k * DX + d) * HX + h0 + tx;
        g_w2t[base] = a0; g_w2t[LVL + base] = a1; g_w2t[2 * LVL + base] = a2;
    }
}

// ---------------------------------------------------------------------------
// Main fused kernel: 256 threads, 1 expert x 128 batch rows per CTA
// ---------------------------------------------------------------------------
__global__ __launch_bounds__(256, 1)
void ae_main(const float* __restrict__ x,
             const float* __restrict__ b1,
             const float* __restrict__ b2)
{
#if AE_TC
    extern __shared__ char smem[];
    const uint32_t sb = smem_u32(smem);
    const int tid = threadIdx.x, wid = tid >> 5, lane = tid & 31;
    const int k = blockIdx.y, b0 = blockIdx.x * BM;

    if (wid == 0) TCGEN05_ALLOC(sb + SM_TMEMPTR, 512);
    if (tid == 0) MBARRIER_INIT(sb + SM_MBAR, 1);
    if (tid < 64) {
        float4 v = ((const float4*)(b1 + (size_t)k * HX))[tid];
        ((float4*)(smem + SM_BIAS1))[tid] = v;
    }
    __syncthreads();
    uint32_t tb;
    asm volatile("ld.shared.b32 %0, [%1];" : "=r"(tb) : "r"(sb + SM_TMEMPTR));

    int phase = 0;
    const int pa[6] = {0, 1, 2, 0, 1, 0};
    const int pb[6] = {0, 0, 0, 1, 1, 2};

    // ================= Stage 1: h = relu(x @ W1k + b1)  (D1 in TMEM) ========
    for (int kc = 0; kc < 16; kc++) {
        for (int t = tid; t < 3072; t += 256) {      // A: 3 x [128 x 64 bf16]
            int l = t >> 10, rem = t & 1023, r = rem >> 3, c = rem & 7;
            uint32_t off = (uint32_t)(r * 128 + c * 16);
            uint32_t dst = sb + SM_A1 + l * 16384 + SW128(off);
            const __nv_bfloat16* src =
                g_xs + ((size_t)l * BX + b0 + r) * DX + kc * 64 + c * 8;
            CP16(dst, src);
        }
        for (int t = tid; t < 6144; t += 256) {      // B: 3 x [256 x 64 bf16]
            int l = t / 2048, rem = t % 2048, r = rem >> 3, c = rem & 7;
            uint32_t off = (uint32_t)(r * 128 + c * 16);
            uint32_t dst = sb + SM_B1 + l * 32768 + SW128(off);
            const __nv_bfloat16* src =
                g_w1t + (((size_t)l * KX + k) * HX + r) * DX + kc * 64 + c * 8;
            CP16(dst, src);
        }
        CP_COMMIT(); CP_WAIT0();
        __syncthreads();
        if (tid == 0) {
            FENCE_PROXY_ASYNC();
            #pragma unroll
            for (int p = 0; p < 6; p++) {
                uint64_t ad = MAKE_DESC(sb + SM_A1 + pa[p] * 16384);
                uint64_t bd = MAKE_DESC(sb + SM_B1 + pb[p] * 32768);
                #pragma unroll
                for (int s = 0; s < 4; s++) {
                    bool en = !(kc == 0 && p == 0 && s == 0);
                    mma_f16_ss(tb + TM_D1, ad + s * 2, bd + s * 2, IDESC1, en);
                }
            }
            TCGEN05_COMMIT(sb + SM_MBAR);
        }
        MBARRIER_WAIT_PARITY(sb + SM_MBAR, phase); phase ^= 1;
        __syncthreads();
    }

    // ============ Epilogue 1: bias+relu, split h -> bf16x3 into TMEM ========
    TCGEN05_FENCE_AFTER();
    if (wid < 4) {
        const uint32_t woff = (uint32_t)wid << 21;
        const float* b1s = (const float*)(smem + SM_BIAS1);
        for (int c0 = 0; c0 < 256; c0 += 32) {
            uint32_t r[32];
            LDTM32(r, tb + TM_D1 + c0);
            TCGEN05_WAIT_LD();
            uint32_t p0[16], p1[16], p2[16];
            #pragma unroll
            for (int t2 = 0; t2 < 16; t2++) {
                float v0 = __uint_as_float(r[2 * t2])     + b1s[c0 + 2 * t2];
                float v1 = __uint_as_float(r[2 * t2 + 1]) + b1s[c0 + 2 * t2 + 1];
                v0 = fmaxf(v0, 0.0f); v1 = fmaxf(v1, 0.0f);
                __nv_bfloat16 a0, a1, a2, c0b, c1b, c2b;
                split3(v0, a0, a1, a2);
                split3(v1, c0b, c1b, c2b);
                p0[t2] = pack2(a0, c0b);
                p1[t2] = pack2(a1, c1b);
                p2[t2] = pack2(a2, c2b);
            }
            STTM16(tb + TM_A0  + (c0 >> 1) + woff, p0);
            STTM16(tb + TM_A1C + (c0 >> 1) + woff, p1);
            STTM16(tb + TM_A2  + (c0 >> 1) + woff, p2);
            TCGEN05_WAIT_ST();
        }
        TCGEN05_FENCE_BEFORE();
    }
    __syncthreads();

    // ================= Stage 2: recon = h @ W2k + b2, err ===================
    float errsum = 0.0f;
    const uint32_t abase[3] = {TM_A0, TM_A1C, TM_A2};

    for (int nc = 0; nc < 8; nc++) {
        for (int t = tid; t < 4096; t += 256) {      // x stage tile [128][128] f32
            int r = t >> 5, c = t & 31;
            uint32_t dst = sb + SM_XS + (uint32_t)(r * 528 + c * 16);
            const float* src = x + (size_t)(b0 + r) * DX + nc * 128 + c * 4;
            CP16(dst, src);
        }
        for (int kc = 0; kc < 4; kc++) {
            for (int t = tid; t < 3072; t += 256) {  // B: 3 x [128 x 64 bf16]
                int l = t >> 10, rem = t & 1023, r = rem >> 3, c = rem & 7;
                uint32_t off = (uint32_t)(r * 128 + c * 16);
                uint32_t dst = sb + SM_A1 + l * 16384 + SW128(off);
                const __nv_bfloat16* src =
                    g_w2t + (((size_t)l * KX + k) * DX + nc * 128 + r) * HX + kc * 64 + c * 8;
                CP16(dst, src);
            }
            CP_COMMIT(); CP_WAIT0();
            __syncthreads();
            if (tid == 0) {
                FENCE_PROXY_ASYNC();
                TCGEN05_FENCE_AFTER();
                #pragma unroll
                for (int p = 0; p < 6; p++) {
                    uint64_t bd = MAKE_DESC(sb + SM_A1 + pb[p] * 16384);
                    #pragma unroll
                    for (int s = 0; s < 4; s++) {
                        bool en = !(kc == 0 && p == 0 && s == 0);
                        uint32_t at = tb + abase[pa[p]] + (kc * 4 + s) * 8;
                        mma_f16_ts(tb + TM_D2, at, bd + s * 2, IDESC2, en);
                    }
                }
                TCGEN05_COMMIT(sb + SM_MBAR);
            }
            MBARRIER_WAIT_PARITY(sb + SM_MBAR, phase); phase ^= 1;
            __syncthreads();
        }

        // Epilogue 2: bias, err vs x, stage recon in smem
        TCGEN05_FENCE_AFTER();
        if (wid < 4) {
            const int row = wid * 32 + lane;
            const float* xs_s = (const float*)(smem + SM_XS);
            float* rc_s = (float*)(smem + SM_RC);
            for (int c0 = 0; c0 < 128; c0 += 32) {
                uint32_t r[32];
                LDTM32(r, tb + TM_D2 + c0);
                TCGEN05_WAIT_LD();
                #pragma unroll
                for (int j = 0; j < 32; j++) {
                    int col = nc * 128 + c0 + j;
                    float v = __uint_as_float(r[j]) + __ldg(b2 + (size_t)k * DX + col);
                    float xv = xs_s[row * 132 + c0 + j];
                    float d = v - xv;
                    errsum = fmaf(d, d, errsum);
                    rc_s[row * 132 + c0 + j] = v;
                }
            }
            TCGEN05_FENCE_BEFORE();
        }
        __syncthreads();
        {   // coalesced recon store
            const float* rc_s = (const float*)(smem + SM_RC);
            for (int rr = wid; rr < 128; rr += 8) {
                float4 v = *(const float4*)(rc_s + rr * 132 + lane * 4);
                *(float4*)(g_recon + ((size_t)k * BX + b0 + rr) * DX + nc * 128 + lane * 4) = v;
            }
        }
        __syncthreads();
    }

    if (wid < 4) {
        int row = wid * 32 + lane;
        g_err[(size_t)k * BX + b0 + row] = errsum * (1.0f / DX);
    }
    __syncthreads();
    if (tid == 0) MBARRIER_INVAL(sb + SM_MBAR);
    __syncthreads();
    if (wid == 0) {
        TCGEN05_RELINQ();
        TCGEN05_DEALLOC(tb, 512);
    }
#else
    // ---------------- Correct scalar fallback (non-arch-specific pass) -------
    // Only runs if the runtime selects the generic cubin. Slow but exact enough
    // (weights reconstructed from bf16x3 splits, error ~2^-24).
    extern __shared__ char smem[];
    float* h_f = (float*)smem;                     // [128][256] = 128 KB
    float* errsh = h_f + BM * HX;                  // [128]
    const int tid = threadIdx.x;
    const int k = blockIdx.y, b0 = blockIdx.x * BM;
    const size_t L1 = (size_t)KX * HX * DX;
    const size_t L2 = (size_t)KX * DX * HX;

    for (int i = tid; i < BM * HX; i += 256) {
        int r = i >> 8, c = i & 255;
        float s = b1[(size_t)k * HX + c];
        const float* xr = x + (size_t)(b0 + r) * DX;
        size_t wb = ((size_t)k * HX + c) * DX;
        for (int d = 0; d < DX; d++) {
            float w = __bfloat162float(g_w1t[wb + d]) +
                      __bfloat162float(g_w1t[L1 + wb + d]) +
                      __bfloat162float(g_w1t[2 * L1 + wb + d]);
            s = fmaf(xr[d], w, s);
        }
        h_f[i] = fmaxf(s, 0.0f);
    }
    __syncthreads();
    if (tid < 128) errsh[tid] = 0.0f;
    __syncthreads();
    for (int i = tid; i < BM * DX; i += 256) {
        int r = i >> 10, c = i & 1023;
        float s = b2[(size_t)k * DX + c];
        size_t wb = ((size_t)k * DX + c) * HX;
        for (int hh = 0; hh < HX; hh++) {
            float w = __bfloat162float(g_w2t[wb + hh]) +
                      __bfloat162float(g_w2t[L2 + wb + hh]) +
                      __bfloat162float(g_w2t[2 * L2 + wb + hh]);
            s = fmaf(h_f[r * HX + hh], w, s);
        }
        g_recon[((size_t)k * BX + b0 + r) * DX + c] = s;
        float d = s - x[(size_t)(b0 + r) * DX + c];
        atomicAdd(&errsh[r], d * d);
    }
    __syncthreads();
    if (tid < 128) g_err[(size_t)k * BX + b0 + tid] = errsh[tid] * (1.0f / DX);
#endif
}

// ---------------------------------------------------------------------------
// Argmin + gather
// ---------------------------------------------------------------------------
__global__ __launch_bounds__(256)
void ae_assign_gather_kernel(float* __restrict__ out)
{
    const int warp = threadIdx.x >> 5;
    const int lane = threadIdx.x & 31;
    const int b = blockIdx.x * 8 + warp;
    if (b >= BX) return;

    float best = g_err[b];
    int bi = 0;
    #pragma unroll
    for (int kk = 1; kk < KX; kk++) {
        float e = g_err[(size_t)kk * BX + b];
        if (e < best) { best = e; bi = kk; }
    }
    const float4* src = (const float4*)(g_recon + ((size_t)bi * BX + b) * DX);
    float4* dst = (float4*)(out + (size_t)b * DX);
    #pragma unroll
    for (int j = 0; j < 8; j++)
        dst[lane + 32 * j] = src[lane + 32 * j];
}

// ---------------------------------------------------------------------------
// Host launcher
// ---------------------------------------------------------------------------
extern "C" void kernel_launch(void* const* d_in, const int* in_sizes, int n_in,
                              void* d_out, int out_size)
{
    const float* x  = (const float*)d_in[0];
    const float* W1 = (const float*)d_in[1];
    const float* b1 = (const float*)d_in[2];
    const float* W2 = (const float*)d_in[3];
    const float* b2 = (const float*)d_in[4];
    float* out = (float*)d_out;

    split_x_kernel<<<(BX * DX / 2 + 255) / 256, 256>>>(x);
    tr_w1_kernel<<<dim3(HX / 32, DX / 32, KX), dim3(32, 8)>>>(W1);
    tr_w2_kernel<<<dim3(DX / 32, HX / 32, KX), dim3(32, 8)>>>(W2);

    cudaFuncSetAttribute(ae_main, cudaFuncAttributeMaxDynamicSharedMemorySize, SMEM_TOTAL);
    ae_main<<<dim3(BX / BM, KX), 256, SMEM_TOTAL>>>(x, b1, b2);

    ae_assign_gather_kernel<<<BX / 8, 256>>>(out);
}